// round 1
// baseline (speedup 1.0000x reference)
#include <cuda_runtime.h>

// Gaussian-splat over-compositing, N pixels x K gaussians.
// 2 pixels per thread packed into f32x2 lanes (FFMA2 path on sm_103a).
// Params preprocessed per-CTA into smem as broadcast f32x2 pairs:
//   q = A*dx^2 + B2*dx*dy + C*dy^2 + log2(alpha_k)   (A,B2,C include -0.5*log2e)
//   e = exp2(q) = alpha_k * exp(-0.5 d^T Sigma^-1 d)
//   w = e*(1-pa); pa' = pa+w; r = 1/(pa'+eps)
//   pc' = pc*(pa*r) + col*(w*r)      (per-step clip is a provable no-op)

#define MAXK 128

typedef unsigned long long u64;

__device__ __forceinline__ u64 pack2(float a, float b) {
    u64 r; asm("mov.b64 %0, {%1, %2};" : "=l"(r) : "f"(a), "f"(b)); return r;
}
__device__ __forceinline__ void unpack2(u64 v, float& a, float& b) {
    asm("mov.b64 {%0, %1}, %2;" : "=f"(a), "=f"(b) : "l"(v));
}
__device__ __forceinline__ u64 fma2(u64 a, u64 b, u64 c) {
    u64 d; asm("fma.rn.f32x2 %0, %1, %2, %3;" : "=l"(d) : "l"(a), "l"(b), "l"(c)); return d;
}
__device__ __forceinline__ u64 add2(u64 a, u64 b) {
    u64 d; asm("add.rn.f32x2 %0, %1, %2;" : "=l"(d) : "l"(a), "l"(b)); return d;
}
__device__ __forceinline__ u64 mul2(u64 a, u64 b) {
    u64 d; asm("mul.rn.f32x2 %0, %1, %2;" : "=l"(d) : "l"(a), "l"(b)); return d;
}
__device__ __forceinline__ float ex2f_(float x) {
    float y; asm("ex2.approx.f32 %0, %1;" : "=f"(y) : "f"(x)); return y;
}
__device__ __forceinline__ float rcpf_(float x) {
    float y; asm("rcp.approx.f32 %0, %1;" : "=f"(y) : "f"(x)); return y;
}

__global__ __launch_bounds__(256)
void gs_splat_kernel(const float* __restrict__ pos,
                     const float* __restrict__ mu,
                     const float* __restrict__ alpha,
                     const float* __restrict__ color,
                     const float* __restrict__ scales,
                     const float* __restrict__ thetas,
                     float4* __restrict__ out,
                     int n, int K)
{
    // per-k: 10 broadcast f32x2 pairs (80 B, 16B-aligned -> 5x LDS.128 per k)
    __shared__ __align__(16) float2 sp[MAXK * 10];

    const float L2E = 1.44269504088896340736f;

    // ---- per-CTA param prep ----
    for (int k = threadIdx.x; k < K; k += blockDim.x) {
        float th = thetas[k];
        float c = cosf(th), s = sinf(th);
        float sx = fmaxf(scales[2 * k + 0], 0.1f);
        float sy = fmaxf(scales[2 * k + 1], 0.1f);
        float ix = 1.0f / (sx * sx);
        float iy = 1.0f / (sy * sy);
        float S00 = c * c * ix + s * s * iy;
        float S01 = c * s * (ix - iy);
        float S11 = s * s * ix + c * c * iy;
        float h = -0.5f * L2E;
        float A  = h * S00;
        float B2 = (2.0f * h) * S01;
        float C  = h * S11;
        float a  = fminf(fmaxf(alpha[k], 0.0f), 1.0f);
        float la = log2f(fmaxf(a, 1e-38f));   // exp2(q+la) == a*exp(-0.5 dSd)
        float c0 = fminf(fmaxf(color[3 * k + 0], 0.0f), 255.0f);
        float c1 = fminf(fmaxf(color[3 * k + 1], 0.0f), 255.0f);
        float c2 = fminf(fmaxf(color[3 * k + 2], 0.0f), 255.0f);
        float mx = mu[2 * k + 0];
        float my = mu[2 * k + 1];
        float2* p = &sp[k * 10];
        p[0] = make_float2(-mx, -mx);
        p[1] = make_float2(-my, -my);
        p[2] = make_float2(A, A);
        p[3] = make_float2(B2, B2);
        p[4] = make_float2(C, C);
        p[5] = make_float2(la, la);
        p[6] = make_float2(c0, c0);
        p[7] = make_float2(c1, c1);
        p[8] = make_float2(c2, c2);
        p[9] = make_float2(0.0f, 0.0f);
    }
    __syncthreads();

    // ---- 2 pixels per thread, coalesced: i0 = base+tid, i1 = i0+blockDim ----
    int base = blockIdx.x * (blockDim.x * 2);
    int i0 = base + threadIdx.x;
    int i1 = i0 + blockDim.x;
    bool v0 = (i0 < n), v1 = (i1 < n);
    float2 P0 = v0 ? ((const float2*)pos)[i0] : make_float2(0.0f, 0.0f);
    float2 P1 = v1 ? ((const float2*)pos)[i1] : make_float2(0.0f, 0.0f);

    u64 px = pack2(P0.x, P1.x);
    u64 py = pack2(P0.y, P1.y);
    u64 pc0 = 0ull, pc1 = 0ull, pc2 = 0ull;
    u64 pa  = 0ull;                       // accumulated alpha
    u64 omp = pack2(1.0f, 1.0f);          // 1 - pa (transmittance)
    const u64 EPS2 = pack2(1e-8f, 1e-8f);
    const u64 NEG1 = pack2(-1.0f, -1.0f);

    const ulonglong2* __restrict__ g = (const ulonglong2*)sp;

#pragma unroll 4
    for (int k = 0; k < K; k++) {
        ulonglong2 g0 = g[k * 5 + 0];   // {-mux2, -muy2}
        ulonglong2 g1 = g[k * 5 + 1];   // {A2, B22}
        ulonglong2 g2 = g[k * 5 + 2];   // {C2, la2}
        ulonglong2 g3 = g[k * 5 + 3];   // {col0, col1}
        ulonglong2 g4 = g[k * 5 + 4];   // {col2, pad}

        u64 dx  = add2(px, g0.x);
        u64 dy  = add2(py, g0.y);
        u64 t1  = mul2(g1.y, dy);            // B2*dy
        u64 t2  = fma2(g1.x, dx, t1);        // A*dx + B2*dy
        u64 dyy = mul2(dy, dy);
        u64 t4  = fma2(g2.x, dyy, g2.y);     // C*dy^2 + log2(alpha)
        u64 q   = fma2(dx, t2, t4);

        float qa, qb; unpack2(q, qa, qb);
        u64 e = pack2(ex2f_(qa), ex2f_(qb)); // alpha_k * gaussian

        u64 w   = mul2(e, omp);              // alpha_k * (1 - pa)
        u64 pan = add2(pa, w);               // new alpha
        u64 d   = add2(pan, EPS2);
        float da, db; unpack2(d, da, db);
        u64 r   = pack2(rcpf_(da), rcpf_(db));

        u64 f  = mul2(pa, r);                // old pa * r
        u64 wr = mul2(w, r);
        pc0 = fma2(pc0, f, mul2(g3.x, wr));
        pc1 = fma2(pc1, f, mul2(g3.y, wr));
        pc2 = fma2(pc2, f, mul2(g4.x, wr));

        omp = fma2(w, NEG1, omp);            // omp -= w
        pa  = pan;
    }

    float a0, a1;  unpack2(pa,  a0, a1);
    float r0, r1;  unpack2(pc0, r0, r1);
    float q0, q1;  unpack2(pc1, q0, q1);
    float b0, b1;  unpack2(pc2, b0, b1);

    if (v0) {
        out[i0] = make_float4(fminf(fmaxf(r0, 0.0f), 255.0f),
                              fminf(fmaxf(q0, 0.0f), 255.0f),
                              fminf(fmaxf(b0, 0.0f), 255.0f),
                              fminf(fmaxf(a0, 0.0f), 1.0f) * 255.0f);
    }
    if (v1) {
        out[i1] = make_float4(fminf(fmaxf(r1, 0.0f), 255.0f),
                              fminf(fmaxf(q1, 0.0f), 255.0f),
                              fminf(fmaxf(b1, 0.0f), 255.0f),
                              fminf(fmaxf(a1, 0.0f), 1.0f) * 255.0f);
    }
}

extern "C" void kernel_launch(void* const* d_in, const int* in_sizes, int n_in,
                              void* d_out, int out_size)
{
    const float* pos    = (const float*)d_in[0];
    const float* mu     = (const float*)d_in[1];
    const float* alpha  = (const float*)d_in[2];
    const float* color  = (const float*)d_in[3];
    const float* scales = (const float*)d_in[4];
    const float* thetas = (const float*)d_in[5];

    int n = in_sizes[0] / 2;     // pixels
    int K = in_sizes[2];         // gaussians
    if (K > MAXK) K = MAXK;      // problem spec: K = 128

    const int threads = 256;
    const int pixPerCta = threads * 2;
    int grid = (n + pixPerCta - 1) / pixPerCta;

    gs_splat_kernel<<<grid, threads>>>(pos, mu, alpha, color, scales, thetas,
                                       (float4*)d_out, n, K);
}

// round 3
// speedup vs baseline: 1.0422x; 1.0422x over previous
#include <cuda_runtime.h>

// Gaussian-splat over-compositing, N pixels x K gaussians, sm_103a.
// Exact-semantics scaled-numerator form (reproduces the reference's eps
// renormalization factors):
//   e   = exp2(A*X2 + B2*XY + C*Y2 + Dx*x + Ey*y + F)   (coeffs fold -0.5*log2e
//                                                        and log2(alpha_k);
//                                                        coords centered at 256)
//   w   = e * omp                 (omp = 1 - pa)
//   u_c = u_c * g + col_c * w     (g = pa/(pa+eps) from PREVIOUS step)
//   pan = pa + w;  omp -= w;  d = pan + eps;  r = rcp(d);  g = pan * r
// Final: pc_c = u_c * r_last;  alpha_out = min(pa,1)*255.
// This equals the reference recurrence pc=(pc*pa+col*w)/(pa'+eps) to ~1ulp/step.
// 2 pixels packed per f32x2 lane pair (FFMA2), 2 pairs (4 pixels) per thread.

#define MAXK 128

typedef unsigned long long u64;

__device__ __forceinline__ u64 pack2(float a, float b) {
    u64 r; asm("mov.b64 %0, {%1, %2};" : "=l"(r) : "f"(a), "f"(b)); return r;
}
__device__ __forceinline__ void unpack2(u64 v, float& a, float& b) {
    asm("mov.b64 {%0, %1}, %2;" : "=f"(a), "=f"(b) : "l"(v));
}
__device__ __forceinline__ u64 fma2(u64 a, u64 b, u64 c) {
    u64 d; asm("fma.rn.f32x2 %0, %1, %2, %3;" : "=l"(d) : "l"(a), "l"(b), "l"(c)); return d;
}
__device__ __forceinline__ u64 add2(u64 a, u64 b) {
    u64 d; asm("add.rn.f32x2 %0, %1, %2;" : "=l"(d) : "l"(a), "l"(b)); return d;
}
__device__ __forceinline__ u64 mul2(u64 a, u64 b) {
    u64 d; asm("mul.rn.f32x2 %0, %1, %2;" : "=l"(d) : "l"(a), "l"(b)); return d;
}
__device__ __forceinline__ float ex2f_(float x) {
    float y; asm("ex2.approx.f32 %0, %1;" : "=f"(y) : "f"(x)); return y;
}
__device__ __forceinline__ float rcpf_(float x) {
    float y; asm("rcp.approx.f32 %0, %1;" : "=f"(y) : "f"(x)); return y;
}

// Per-pair state for 2 packed pixels.
struct PairState {
    u64 x, y, x2, xy, y2;          // centered coords + quadratic monomials
    u64 u0, u1, u2;                // scaled color numerators
    u64 pa, omp, g, r;             // alpha, 1-alpha, carry factor, last rcp
};

__device__ __forceinline__ void pair_init(PairState& S, float2 P0, float2 P1) {
    float ax = P0.x - 256.0f, ay = P0.y - 256.0f;
    float bx = P1.x - 256.0f, by = P1.y - 256.0f;
    S.x  = pack2(ax, bx);
    S.y  = pack2(ay, by);
    S.x2 = mul2(S.x, S.x);
    S.xy = mul2(S.x, S.y);
    S.y2 = mul2(S.y, S.y);
    S.u0 = S.u1 = S.u2 = 0ull;
    S.pa = 0ull;
    S.g  = 0ull;
    S.r  = 0ull;
    S.omp = pack2(1.0f, 1.0f);
}

__device__ __forceinline__ void pair_step(PairState& S,
                                          ulonglong2 g0, ulonglong2 g1,
                                          ulonglong2 g2, ulonglong2 g3,
                                          ulonglong2 g4,
                                          u64 EPS2, u64 NEG1) {
    // q = A*x2 + B2*xy + C*y2 + Dx*x + Ey*y + F
    u64 t = fma2(g2.x, S.y, g2.y);       // Ey*y + F
    t = fma2(g1.y, S.x, t);              // + Dx*x
    t = fma2(g1.x, S.y2, t);             // + C*y2
    t = fma2(g0.y, S.xy, t);             // + B2*xy
    u64 q = fma2(g0.x, S.x2, t);         // + A*x2

    float qa, qb; unpack2(q, qa, qb);
    u64 e = pack2(ex2f_(qa), ex2f_(qb)); // alpha_k * gaussian

    u64 w   = mul2(e, S.omp);            // contribution weight
    u64 cw0 = mul2(g3.x, w);
    u64 cw1 = mul2(g3.y, w);
    u64 cw2 = mul2(g4.x, w);
    S.u0 = fma2(S.u0, S.g, cw0);         // u = u*g_{prev} + col*w
    S.u1 = fma2(S.u1, S.g, cw1);
    S.u2 = fma2(S.u2, S.g, cw2);

    u64 pan = add2(S.pa, w);
    S.omp = fma2(w, NEG1, S.omp);
    u64 d = add2(pan, EPS2);
    float da, db; unpack2(d, da, db);
    S.r = pack2(rcpf_(da), rcpf_(db));
    S.g = mul2(pan, S.r);
    S.pa = pan;
}

__device__ __forceinline__ void pair_emit(const PairState& S, float4* out,
                                          int i0, int i1, bool v0, bool v1) {
    float r0, r1;  unpack2(S.r,  r0, r1);
    float a0, a1;  unpack2(S.pa, a0, a1);
    float u00, u01; unpack2(S.u0, u00, u01);
    float u10, u11; unpack2(S.u1, u10, u11);
    float u20, u21; unpack2(S.u2, u20, u21);
    if (v0) {
        out[i0] = make_float4(fminf(fmaxf(u00 * r0, 0.0f), 255.0f),
                              fminf(fmaxf(u10 * r0, 0.0f), 255.0f),
                              fminf(fmaxf(u20 * r0, 0.0f), 255.0f),
                              fminf(fmaxf(a0, 0.0f), 1.0f) * 255.0f);
    }
    if (v1) {
        out[i1] = make_float4(fminf(fmaxf(u01 * r1, 0.0f), 255.0f),
                              fminf(fmaxf(u11 * r1, 0.0f), 255.0f),
                              fminf(fmaxf(u21 * r1, 0.0f), 255.0f),
                              fminf(fmaxf(a1, 0.0f), 1.0f) * 255.0f);
    }
}

template<int KT>
__global__ __launch_bounds__(128)
void gs_splat_kernel(const float* __restrict__ pos,
                     const float* __restrict__ mu,
                     const float* __restrict__ alpha,
                     const float* __restrict__ color,
                     const float* __restrict__ scales,
                     const float* __restrict__ thetas,
                     float4* __restrict__ out,
                     int n, int K)
{
    const int KK = (KT > 0) ? KT : MAXK;
    // per-k: 10 broadcast f32x2 pairs (80 B) -> 5x LDS.128 per k
    __shared__ __align__(16) float2 sp[MAXK * 10];

    const float L2E = 1.44269504088896340736f;

    // ---- per-CTA param prep ----
    for (int k = threadIdx.x; k < K; k += blockDim.x) {
        float th = thetas[k];
        float c = cosf(th), s = sinf(th);
        float sx = fmaxf(scales[2 * k + 0], 0.1f);
        float sy = fmaxf(scales[2 * k + 1], 0.1f);
        float ix = 1.0f / (sx * sx);
        float iy = 1.0f / (sy * sy);
        float S00 = c * c * ix + s * s * iy;
        float S01 = c * s * (ix - iy);
        float S11 = s * s * ix + c * c * iy;
        float h = -0.5f * L2E;
        float A  = h * S00;
        float B2 = (2.0f * h) * S01;
        float C  = h * S11;
        float a  = fminf(fmaxf(alpha[k], 0.0f), 1.0f);
        float la = log2f(fmaxf(a, 1e-38f));
        float c0 = fminf(fmaxf(color[3 * k + 0], 0.0f), 255.0f);
        float c1 = fminf(fmaxf(color[3 * k + 1], 0.0f), 255.0f);
        float c2 = fminf(fmaxf(color[3 * k + 2], 0.0f), 255.0f);
        float mx = mu[2 * k + 0] - 256.0f;   // centered
        float my = mu[2 * k + 1] - 256.0f;
        float Dx = -(2.0f * A * mx + B2 * my);
        float Ey = -(B2 * mx + 2.0f * C * my);
        float F  = (A * mx * mx + B2 * mx * my + C * my * my) + la;
        float2* p = &sp[k * 10];
        p[0] = make_float2(A, A);
        p[1] = make_float2(B2, B2);
        p[2] = make_float2(C, C);
        p[3] = make_float2(Dx, Dx);
        p[4] = make_float2(Ey, Ey);
        p[5] = make_float2(F, F);
        p[6] = make_float2(c0, c0);
        p[7] = make_float2(c1, c1);
        p[8] = make_float2(c2, c2);
        p[9] = make_float2(0.0f, 0.0f);
    }
    __syncthreads();

    // ---- 4 pixels per thread (2 packed pairs), coalesced ----
    int base = blockIdx.x * (blockDim.x * 4);
    int i0 = base + threadIdx.x;
    int i1 = i0 + blockDim.x;
    int i2 = i0 + 2 * blockDim.x;
    int i3 = i0 + 3 * blockDim.x;
    bool v0 = (i0 < n), v1 = (i1 < n), v2 = (i2 < n), v3 = (i3 < n);
    const float2* pos2 = (const float2*)pos;
    float2 P0 = v0 ? pos2[i0] : make_float2(0.0f, 0.0f);
    float2 P1 = v1 ? pos2[i1] : make_float2(0.0f, 0.0f);
    float2 P2 = v2 ? pos2[i2] : make_float2(0.0f, 0.0f);
    float2 P3 = v3 ? pos2[i3] : make_float2(0.0f, 0.0f);

    PairState Sa, Sb;
    pair_init(Sa, P0, P1);
    pair_init(Sb, P2, P3);

    const u64 EPS2 = pack2(1e-8f, 1e-8f);
    const u64 NEG1 = pack2(-1.0f, -1.0f);
    const ulonglong2* __restrict__ g = (const ulonglong2*)sp;

#pragma unroll 4
    for (int k = 0; k < KK; k++) {
        ulonglong2 g0 = g[k * 5 + 0];   // {A2,  B22}
        ulonglong2 g1 = g[k * 5 + 1];   // {C2,  Dx2}
        ulonglong2 g2 = g[k * 5 + 2];   // {Ey2, F2}
        ulonglong2 g3 = g[k * 5 + 3];   // {c02, c12}
        ulonglong2 g4 = g[k * 5 + 4];   // {c22, pad}
        pair_step(Sa, g0, g1, g2, g3, g4, EPS2, NEG1);
        pair_step(Sb, g0, g1, g2, g3, g4, EPS2, NEG1);
    }

    pair_emit(Sa, out, i0, i1, v0, v1);
    pair_emit(Sb, out, i2, i3, v2, v3);
}

extern "C" void kernel_launch(void* const* d_in, const int* in_sizes, int n_in,
                              void* d_out, int out_size)
{
    const float* pos    = (const float*)d_in[0];
    const float* mu     = (const float*)d_in[1];
    const float* alpha  = (const float*)d_in[2];
    const float* color  = (const float*)d_in[3];
    const float* scales = (const float*)d_in[4];
    const float* thetas = (const float*)d_in[5];

    int n = in_sizes[0] / 2;     // pixels
    int K = in_sizes[2];         // gaussians
    if (K > MAXK) K = MAXK;

    const int threads = 128;
    const int pixPerCta = threads * 4;
    int grid = (n + pixPerCta - 1) / pixPerCta;

    if (K == 128) {
        gs_splat_kernel<128><<<grid, threads>>>(pos, mu, alpha, color, scales,
                                                thetas, (float4*)d_out, n, K);
    } else {
        gs_splat_kernel<0><<<grid, threads>>>(pos, mu, alpha, color, scales,
                                              thetas, (float4*)d_out, n, K);
    }
}